// round 4
// baseline (speedup 1.0000x reference)
#include <cuda_runtime.h>
#include <math.h>

#define BB    64
#define NN    2048
#define DIM   768
#define POOL  1024
#define LEN   16
#define ROW   2080          // 2*LEN + NN
#define NCHUNK 16
#define CH    128           // NN / NCHUNK
#define D4    192           // DIM / 4
#define PCH   4             // prompt chunks (POOL / 256)

// ---------------- scratch (device globals; only referenced in device code) --
__device__ __align__(16) float g_part[NCHUNK * BB * DIM];
__device__ __align__(16) float g_xnorm[BB * DIM];
__device__ __align__(16) float g_resq[BB * DIM];
__device__ __align__(16) float g_pn[POOL * DIM];
__device__ __align__(16) float g_rn[POOL * DIM];
__device__ float g_cval[BB * PCH];
__device__ int   g_cidx[BB * PCH];
__device__ float g_rcval[BB * PCH];
__device__ int   g_rcidx[BB * PCH];
__device__ int   g_idx[BB];
__device__ float g_maxsim[BB];

__device__ __forceinline__ float warp_sum(float v) {
    #pragma unroll
    for (int o = 16; o > 0; o >>= 1) v += __shfl_xor_sync(0xffffffffu, v, o);
    return v;
}

// ---------------------------------------------------------------------------
// K1: stream x_embed -> out[:, 32:, :] while accumulating partial sums.
// Explicit 8-deep load batching (MLP=8) + streaming cache hints.
// grid (BB, NCHUNK), 192 threads.
// ---------------------------------------------------------------------------
__global__ void k_mean_copy(const float* __restrict__ x, float* __restrict__ out) {
    const int t = threadIdx.x;            // 0..191
    const int b = blockIdx.x;
    const int z = blockIdx.y;

    const float4* src = reinterpret_cast<const float4*>(
        x + ((size_t)b * NN + (size_t)z * CH) * DIM) + t;
    float4* dst = reinterpret_cast<float4*>(
        out + ((size_t)b * ROW + 2 * LEN + (size_t)z * CH) * DIM) + t;

    float4 s = make_float4(0.f, 0.f, 0.f, 0.f);
    for (int n0 = 0; n0 < CH; n0 += 8) {
        float4 v[8];
        #pragma unroll
        for (int k = 0; k < 8; k++)
            v[k] = __ldcs(src + (size_t)(n0 + k) * D4);
        #pragma unroll
        for (int k = 0; k < 8; k++) {
            s.x += v[k].x; s.y += v[k].y; s.z += v[k].z; s.w += v[k].w;
            __stcs(dst + (size_t)(n0 + k) * D4, v[k]);
        }
    }
    reinterpret_cast<float4*>(g_part)[((size_t)z * BB + b) * D4 + t] = s;
}

// ---------------------------------------------------------------------------
// K2: normalize rows (prompt_key -> g_pn, residual_key -> g_rn, mean -> g_xnorm)
// ---------------------------------------------------------------------------
__global__ void k_normalize(const float* __restrict__ pk,
                            const float* __restrict__ rpk) {
    const int r = blockIdx.x;
    const int t = threadIdx.x;            // 0..191
    const int w = t >> 5, lane = t & 31;

    float4 v;
    float* dst;
    if (r < POOL) {
        v = reinterpret_cast<const float4*>(pk + (size_t)r * DIM)[t];
        dst = g_pn + (size_t)r * DIM;
    } else if (r < 2 * POOL) {
        v = reinterpret_cast<const float4*>(rpk + (size_t)(r - POOL) * DIM)[t];
        dst = g_rn + (size_t)(r - POOL) * DIM;
    } else {
        const int b = r - 2 * POOL;
        float4 acc = make_float4(0.f, 0.f, 0.f, 0.f);
        #pragma unroll
        for (int z = 0; z < NCHUNK; z++) {
            float4 p = reinterpret_cast<const float4*>(g_part)[((size_t)z * BB + b) * D4 + t];
            acc.x += p.x; acc.y += p.y; acc.z += p.z; acc.w += p.w;
        }
        const float inv = 1.0f / (float)NN;
        v = make_float4(acc.x * inv, acc.y * inv, acc.z * inv, acc.w * inv);
        dst = g_xnorm + (size_t)b * DIM;
    }

    float ss = v.x * v.x + v.y * v.y + v.z * v.z + v.w * v.w;
    ss = warp_sum(ss);
    __shared__ float sm[6];
    __shared__ float s_rinv;
    if (lane == 0) sm[w] = ss;
    __syncthreads();
    if (t == 0) {
        float tot = 0.f;
        #pragma unroll
        for (int i = 0; i < 6; i++) tot += sm[i];
        s_rinv = 1.0f / sqrtf(fmaxf(tot, 1e-12f));
    }
    __syncthreads();
    const float rinv = s_rinv;
    reinterpret_cast<float4*>(dst)[t] = make_float4(v.x * rinv, v.y * rinv, v.z * rinv, v.w * rinv);
}

// ---------------------------------------------------------------------------
// K3/K5: partial argmax, one prompt per thread. grid (BB, PCH), 256 threads.
// which=0: keys=g_pn, q=g_xnorm -> g_cval/g_cidx
// which=1: keys=g_rn, q=g_resq  -> g_rcval/g_rcidx
// ---------------------------------------------------------------------------
__global__ void k_argmax_part(int which) {
    const int b = blockIdx.x;
    const int pc = blockIdx.y;
    const int t = threadIdx.x;            // 0..255

    const float* keys  = which ? g_rn   : g_pn;
    const float* qbase = which ? g_resq : g_xnorm;
    float* cval = which ? g_rcval : g_cval;
    int*   cidx = which ? g_rcidx : g_cidx;

    __shared__ float4 qs[D4];
    if (t < D4) qs[t] = reinterpret_cast<const float4*>(qbase + (size_t)b * DIM)[t];
    __syncthreads();

    const int p = pc * 256 + t;
    const float4* row = reinterpret_cast<const float4*>(keys + (size_t)p * DIM);

    float a0 = 0.f, a1 = 0.f, a2 = 0.f, a3 = 0.f;
    #pragma unroll 4
    for (int j = 0; j < D4; j += 4) {
        float4 r0 = row[j + 0], q0 = qs[j + 0];
        float4 r1 = row[j + 1], q1 = qs[j + 1];
        float4 r2 = row[j + 2], q2 = qs[j + 2];
        float4 r3 = row[j + 3], q3 = qs[j + 3];
        a0 += r0.x * q0.x + r0.y * q0.y + r0.z * q0.z + r0.w * q0.w;
        a1 += r1.x * q1.x + r1.y * q1.y + r1.z * q1.z + r1.w * q1.w;
        a2 += r2.x * q2.x + r2.y * q2.y + r2.z * q2.z + r2.w * q2.w;
        a3 += r3.x * q3.x + r3.y * q3.y + r3.z * q3.z + r3.w * q3.w;
    }
    float v = (a0 + a1) + (a2 + a3);

    __shared__ float sv[256];
    __shared__ int   si[256];
    sv[t] = v; si[t] = p;
    __syncthreads();
    #pragma unroll
    for (int s = 128; s > 0; s >>= 1) {
        if (t < s) {
            float ov = sv[t + s]; int oi = si[t + s];
            if (ov > sv[t] || (ov == sv[t] && oi < si[t])) { sv[t] = ov; si[t] = oi; }
        }
        __syncthreads();
    }
    if (t == 0) { cval[b * PCH + pc] = sv[0]; cidx[b * PCH + pc] = si[0]; }
}

// ---------------------------------------------------------------------------
// K4: reduce first-level candidates, build residual query. grid BB, 192 thr.
// ---------------------------------------------------------------------------
__global__ void k_reduce_res(const float* __restrict__ pk) {
    const int b = blockIdx.x;
    const int t = threadIdx.x;            // 0..191
    __shared__ int s_idx;
    if (t == 0) {
        float bv = g_cval[b * PCH]; int bi = g_cidx[b * PCH];
        #pragma unroll
        for (int c = 1; c < PCH; c++) {
            float ov = g_cval[b * PCH + c]; int oi = g_cidx[b * PCH + c];
            if (ov > bv || (ov == bv && oi < bi)) { bv = ov; bi = oi; }
        }
        g_idx[b] = bi;
        g_maxsim[b] = bv;
        s_idx = bi;
    }
    __syncthreads();
    const int idx = s_idx;
    float4 a  = reinterpret_cast<const float4*>(pk + (size_t)idx * DIM)[t];
    float4 xn = reinterpret_cast<const float4*>(g_xnorm + (size_t)b * DIM)[t];
    reinterpret_cast<float4*>(g_resq + (size_t)b * DIM)[t] =
        make_float4(a.x - xn.x, a.y - xn.y, a.z - xn.z, a.w - xn.w);
}

// ---------------------------------------------------------------------------
// K6: gather winning prompts + scalar loss. grid BB, 256 threads.
// ---------------------------------------------------------------------------
__device__ __forceinline__ void reduce_rcand(int b, float* bv, int* bi) {
    float v = g_rcval[b * PCH]; int i = g_rcidx[b * PCH];
    #pragma unroll
    for (int c = 1; c < PCH; c++) {
        float ov = g_rcval[b * PCH + c]; int oi = g_rcidx[b * PCH + c];
        if (ov > v || (ov == v && oi < i)) { v = ov; i = oi; }
    }
    *bv = v; *bi = i;
}

__global__ void k_gather(const float* __restrict__ prompt,
                         const float* __restrict__ rprompt,
                         float* __restrict__ out,
                         long long out_size) {
    const int b = blockIdx.x;
    const int t = threadIdx.x;            // 256 threads
    __shared__ int s_ridx;
    if (t == 0) {
        float rv; int ri;
        reduce_rcand(b, &rv, &ri);
        s_ridx = ri;
    }
    __syncthreads();
    const int idx  = g_idx[b];
    const int ridx = s_ridx;

    const float4* s1 = reinterpret_cast<const float4*>(rprompt + (size_t)ridx * LEN * DIM);
    const float4* s2 = reinterpret_cast<const float4*>(prompt  + (size_t)idx  * LEN * DIM);
    float4* dst = reinterpret_cast<float4*>(out + (size_t)b * ROW * DIM);

    const int SEG = LEN * DIM / 4;        // 3072
    #pragma unroll 4
    for (int i = t; i < SEG; i += 256) dst[i] = s1[i];
    #pragma unroll 4
    for (int i = t; i < SEG; i += 256) dst[SEG + i] = s2[i];

    if (b == 0 && t == 0) {
        float s = 0.f;
        for (int i = 0; i < BB; i++) {
            float rv; int ri;
            reduce_rcand(i, &rv, &ri);
            s += g_maxsim[i] + rv;
        }
        s *= (1.0f / (float)BB);
        const size_t np = (size_t)BB * ROW * DIM;
        if ((size_t)out_size > np) out[(size_t)out_size - 1] = s;
    }
}

// ---------------------------------------------------------------------------
extern "C" void kernel_launch(void* const* d_in, const int* in_sizes, int n_in,
                              void* d_out, int out_size) {
    const float* x       = (const float*)d_in[0];
    const float* prompt  = (const float*)d_in[1];
    const float* pk      = (const float*)d_in[2];
    const float* rprompt = (const float*)d_in[3];
    const float* rpk     = (const float*)d_in[4];
    float* out = (float*)d_out;

    k_mean_copy<<<dim3(BB, NCHUNK), D4>>>(x, out);
    k_normalize<<<2 * POOL + BB, D4>>>(pk, rpk);
    k_argmax_part<<<dim3(BB, PCH), 256>>>(0);
    k_reduce_res<<<BB, D4>>>(pk);
    k_argmax_part<<<dim3(BB, PCH), 256>>>(1);
    k_gather<<<BB, 256>>>(prompt, rprompt, out, (long long)out_size);
}

// round 5
// speedup vs baseline: 1.3140x; 1.3140x over previous
#include <cuda_runtime.h>
#include <math.h>

#define BB    64
#define NN    2048
#define DIM   768
#define POOL  1024
#define LEN   16
#define ROW   2080          // 2*LEN + NN
#define NCHUNK 16
#define CH    128           // NN / NCHUNK
#define D4    192           // DIM / 4
#define QSTR  193           // smem query row stride in float4 (=772 floats, bank-conflict-free)

// ---------------- scratch (device globals; only referenced in device code) --
__device__ __align__(16) float g_part[NCHUNK * BB * DIM];
__device__ __align__(16) float g_xnorm[BB * DIM];
__device__ __align__(16) float g_resq[BB * DIM];
__device__ __align__(16) float g_sim1[POOL * BB];
__device__ __align__(16) float g_sim2[POOL * BB];
__device__ int   g_idx[BB];
__device__ int   g_ridx[BB];
__device__ float g_maxsim[BB];
__device__ float g_rmax[BB];

__device__ __forceinline__ float warp_sum(float v) {
    #pragma unroll
    for (int o = 16; o > 0; o >>= 1) v += __shfl_xor_sync(0xffffffffu, v, o);
    return v;
}

// ---------------------------------------------------------------------------
// K1: stream x_embed -> out[:, 32:, :] while accumulating partial sums.
// grid (BB, NCHUNK), 192 threads.
// ---------------------------------------------------------------------------
__global__ void k_mean_copy(const float* __restrict__ x, float* __restrict__ out) {
    const int t = threadIdx.x;            // 0..191
    const int b = blockIdx.x;
    const int z = blockIdx.y;

    const float4* src = reinterpret_cast<const float4*>(
        x + ((size_t)b * NN + (size_t)z * CH) * DIM) + t;
    float4* dst = reinterpret_cast<float4*>(
        out + ((size_t)b * ROW + 2 * LEN + (size_t)z * CH) * DIM) + t;

    float4 s = make_float4(0.f, 0.f, 0.f, 0.f);
    for (int n0 = 0; n0 < CH; n0 += 8) {
        float4 v[8];
        #pragma unroll
        for (int k = 0; k < 8; k++)
            v[k] = __ldcs(src + (size_t)(n0 + k) * D4);
        #pragma unroll
        for (int k = 0; k < 8; k++) {
            s.x += v[k].x; s.y += v[k].y; s.z += v[k].z; s.w += v[k].w;
            __stcs(dst + (size_t)(n0 + k) * D4, v[k]);
        }
    }
    reinterpret_cast<float4*>(g_part)[((size_t)z * BB + b) * D4 + t] = s;
}

// ---------------------------------------------------------------------------
// K2: finalize mean + l2-normalize -> g_xnorm. grid BB, 192 threads.
// ---------------------------------------------------------------------------
__global__ void k_xnorm() {
    const int b = blockIdx.x;
    const int t = threadIdx.x;            // 0..191
    const int w = t >> 5, lane = t & 31;

    float4 acc = make_float4(0.f, 0.f, 0.f, 0.f);
    #pragma unroll
    for (int z = 0; z < NCHUNK; z++) {
        float4 p = reinterpret_cast<const float4*>(g_part)[((size_t)z * BB + b) * D4 + t];
        acc.x += p.x; acc.y += p.y; acc.z += p.z; acc.w += p.w;
    }
    const float inv = 1.0f / (float)NN;
    float4 v = make_float4(acc.x * inv, acc.y * inv, acc.z * inv, acc.w * inv);

    float ss = v.x * v.x + v.y * v.y + v.z * v.z + v.w * v.w;
    ss = warp_sum(ss);
    __shared__ float sm[6];
    __shared__ float s_rinv;
    if (lane == 0) sm[w] = ss;
    __syncthreads();
    if (t == 0) {
        float tot = 0.f;
        #pragma unroll
        for (int i = 0; i < 6; i++) tot += sm[i];
        s_rinv = 1.0f / sqrtf(fmaxf(tot, 1e-12f));
    }
    __syncthreads();
    const float rinv = s_rinv;
    reinterpret_cast<float4*>(g_xnorm + (size_t)b * DIM)[t] =
        make_float4(v.x * rinv, v.y * rinv, v.z * rinv, v.w * rinv);
}

// ---------------------------------------------------------------------------
// K3/K5: tiled sim GEMM with fused key normalization.
// grid (64 pblocks x 2 btiles), 256 threads (8 warps, 2 prompts per warp).
// which=0: q=g_xnorm -> g_sim1 ; which=1: q=g_resq -> g_sim2.
// sim[p*BB + b] = (1/||key_p||) * (key_p . q_b)
// ---------------------------------------------------------------------------
__global__ void k_sim(const float* __restrict__ keys, int which) {
    const int pb = blockIdx.x;            // 16 prompts per block
    const int bt = blockIdx.y;            // 32 queries per tile
    const int t = threadIdx.x;
    const int w = t >> 5, lane = t & 31;

    extern __shared__ float4 sq[];        // [32][QSTR] float4
    const float* qbase = which ? g_resq : g_xnorm;
    float* simout = which ? g_sim2 : g_sim1;

    for (int i = t; i < 32 * D4; i += 256) {
        const int r = i / D4, c = i % D4;
        sq[r * QSTR + c] =
            reinterpret_cast<const float4*>(qbase + (size_t)(bt * 32 + r) * DIM)[c];
    }
    __syncthreads();

    const int p0 = pb * 16 + w * 2;
    const float4* k0 = reinterpret_cast<const float4*>(keys + (size_t)p0 * DIM);
    const float4* k1 = k0 + D4;

    // key norms (coalesced pass + warp reduce)
    float s0 = 0.f, s1 = 0.f;
    #pragma unroll
    for (int jj = 0; jj < 6; jj++) {
        float4 a = k0[lane + 32 * jj];
        s0 += a.x * a.x + a.y * a.y + a.z * a.z + a.w * a.w;
        float4 c = k1[lane + 32 * jj];
        s1 += c.x * c.x + c.y * c.y + c.z * c.z + c.w * c.w;
    }
    s0 = warp_sum(s0); s1 = warp_sum(s1);
    const float r0 = 1.0f / sqrtf(fmaxf(s0, 1e-12f));
    const float r1 = 1.0f / sqrtf(fmaxf(s1, 1e-12f));

    // lane owns query row (bt*32 + lane); keys read via uniform (broadcast) loads
    const float4* q = sq + (size_t)lane * QSTR;
    float a0 = 0.f, a1 = 0.f, b0 = 0.f, b1 = 0.f;
    #pragma unroll 4
    for (int j = 0; j < D4; j++) {
        float4 ka = k0[j];
        float4 kb = k1[j];
        float4 qq = q[j];
        a0 += ka.x * qq.x + ka.y * qq.y;
        a1 += ka.z * qq.z + ka.w * qq.w;
        b0 += kb.x * qq.x + kb.y * qq.y;
        b1 += kb.z * qq.z + kb.w * qq.w;
    }
    const int b = bt * 32 + lane;
    simout[(size_t)p0 * BB + b]       = r0 * (a0 + a1);
    simout[(size_t)(p0 + 1) * BB + b] = r1 * (b0 + b1);
}

// ---------------------------------------------------------------------------
// K4/K6: per-b argmax over sim column (tie -> lowest p), optional resq build.
// grid BB, 256 threads.
// which=0: g_sim1 -> g_idx/g_maxsim + build g_resq = pk[idx]-xnorm
// which=1: g_sim2 -> g_ridx/g_rmax
// ---------------------------------------------------------------------------
__global__ void k_pick(const float* __restrict__ pk, int which) {
    const int b = blockIdx.x;
    const int t = threadIdx.x;            // 0..255
    const float* sim = which ? g_sim2 : g_sim1;

    float best = -3.4e38f; int bi = 0;
    #pragma unroll
    for (int p = t; p < POOL; p += 256) {
        float v = sim[(size_t)p * BB + b];
        if (v > best) { best = v; bi = p; }   // ascending p -> lowest index kept on tie
    }

    __shared__ float sv[256];
    __shared__ int   si[256];
    sv[t] = best; si[t] = bi;
    __syncthreads();
    #pragma unroll
    for (int s = 128; s > 0; s >>= 1) {
        if (t < s) {
            float ov = sv[t + s]; int oi = si[t + s];
            if (ov > sv[t] || (ov == sv[t] && oi < si[t])) { sv[t] = ov; si[t] = oi; }
        }
        __syncthreads();
    }

    __shared__ int s_idx;
    if (t == 0) {
        if (which == 0) { g_idx[b] = si[0]; g_maxsim[b] = sv[0]; }
        else            { g_ridx[b] = si[0]; g_rmax[b] = sv[0]; }
        s_idx = si[0];
    }
    if (which == 0) {
        __syncthreads();
        const int idx = s_idx;
        if (t < D4) {
            float4 a  = reinterpret_cast<const float4*>(pk + (size_t)idx * DIM)[t];
            float4 xn = reinterpret_cast<const float4*>(g_xnorm + (size_t)b * DIM)[t];
            reinterpret_cast<float4*>(g_resq + (size_t)b * DIM)[t] =
                make_float4(a.x - xn.x, a.y - xn.y, a.z - xn.z, a.w - xn.w);
        }
    }
}

// ---------------------------------------------------------------------------
// K7: gather winning prompts + scalar loss. grid BB, 256 threads.
// ---------------------------------------------------------------------------
__global__ void k_gather(const float* __restrict__ prompt,
                         const float* __restrict__ rprompt,
                         float* __restrict__ out,
                         long long out_size) {
    const int b = blockIdx.x;
    const int t = threadIdx.x;            // 256 threads
    const int idx  = g_idx[b];
    const int ridx = g_ridx[b];

    const float4* s1 = reinterpret_cast<const float4*>(rprompt + (size_t)ridx * LEN * DIM);
    const float4* s2 = reinterpret_cast<const float4*>(prompt  + (size_t)idx  * LEN * DIM);
    float4* dst = reinterpret_cast<float4*>(out + (size_t)b * ROW * DIM);

    const int SEG = LEN * DIM / 4;        // 3072
    #pragma unroll 4
    for (int i = t; i < SEG; i += 256) dst[i] = s1[i];
    #pragma unroll 4
    for (int i = t; i < SEG; i += 256) dst[SEG + i] = s2[i];

    if (b == 0 && t == 0) {
        float s = 0.f;
        for (int i = 0; i < BB; i++) s += g_maxsim[i] + g_rmax[i];
        s *= (1.0f / (float)BB);
        const size_t np = (size_t)BB * ROW * DIM;
        if ((size_t)out_size > np) out[(size_t)out_size - 1] = s;
    }
}

// ---------------------------------------------------------------------------
extern "C" void kernel_launch(void* const* d_in, const int* in_sizes, int n_in,
                              void* d_out, int out_size) {
    const float* x       = (const float*)d_in[0];
    const float* prompt  = (const float*)d_in[1];
    const float* pk      = (const float*)d_in[2];
    const float* rprompt = (const float*)d_in[3];
    const float* rpk     = (const float*)d_in[4];
    float* out = (float*)d_out;

    const int SIM_SMEM = 32 * QSTR * 16;  // 98816 bytes
    static int attr_done = 0;
    if (!attr_done) {
        cudaFuncSetAttribute(k_sim, cudaFuncAttributeMaxDynamicSharedMemorySize, SIM_SMEM);
        attr_done = 1;
    }

    k_mean_copy<<<dim3(BB, NCHUNK), D4>>>(x, out);
    k_xnorm<<<BB, D4>>>();
    k_sim<<<dim3(64, 2), 256, SIM_SMEM>>>(pk, 0);
    k_pick<<<BB, 256>>>(pk, 0);
    k_sim<<<dim3(64, 2), 256, SIM_SMEM>>>(rpk, 1);
    k_pick<<<BB, 256>>>(pk, 1);
    k_gather<<<BB, 256>>>(prompt, rprompt, out, (long long)out_size);
}

// round 6
// speedup vs baseline: 1.3265x; 1.0095x over previous
#include <cuda_runtime.h>
#include <math.h>

#define BB    64
#define NN    2048
#define DIM   768
#define POOL  1024
#define LEN   16
#define ROW   2080          // 2*LEN + NN
#define NCHUNK 16
#define CH    128           // NN / NCHUNK
#define D4    192           // DIM / 4
#define QSTR  193           // smem query row stride in float4 (=772 floats, bank-conflict-free)

// ---------------- scratch (device globals; only referenced in device code) --
__device__ __align__(16) float g_part[NCHUNK * BB * DIM];
__device__ __align__(16) float g_xnorm[BB * DIM];
__device__ __align__(16) float g_resq[BB * DIM];
__device__ __align__(16) float g_sim1[POOL * BB];
__device__ __align__(16) float g_sim2[POOL * BB];
__device__ int   g_idx[BB];
__device__ int   g_ridx[BB];
__device__ float g_maxsim[BB];
__device__ float g_rmax[BB];

__device__ __forceinline__ float warp_sum(float v) {
    #pragma unroll
    for (int o = 16; o > 0; o >>= 1) v += __shfl_xor_sync(0xffffffffu, v, o);
    return v;
}

// ---------------------------------------------------------------------------
// K1: stream x_embed -> out[:, 32:, :] while accumulating partial sums.
// grid (BB, NCHUNK), 192 threads.
// ---------------------------------------------------------------------------
__global__ void k_mean_copy(const float* __restrict__ x, float* __restrict__ out) {
    const int t = threadIdx.x;            // 0..191
    const int b = blockIdx.x;
    const int z = blockIdx.y;

    const float4* src = reinterpret_cast<const float4*>(
        x + ((size_t)b * NN + (size_t)z * CH) * DIM) + t;
    float4* dst = reinterpret_cast<float4*>(
        out + ((size_t)b * ROW + 2 * LEN + (size_t)z * CH) * DIM) + t;

    float4 s = make_float4(0.f, 0.f, 0.f, 0.f);
    for (int n0 = 0; n0 < CH; n0 += 8) {
        float4 v[8];
        #pragma unroll
        for (int k = 0; k < 8; k++)
            v[k] = __ldcs(src + (size_t)(n0 + k) * D4);
        #pragma unroll
        for (int k = 0; k < 8; k++) {
            s.x += v[k].x; s.y += v[k].y; s.z += v[k].z; s.w += v[k].w;
            __stcs(dst + (size_t)(n0 + k) * D4, v[k]);
        }
    }
    reinterpret_cast<float4*>(g_part)[((size_t)z * BB + b) * D4 + t] = s;
}

// ---------------------------------------------------------------------------
// K2: finalize mean + l2-normalize -> g_xnorm. grid BB, 192 threads.
// ---------------------------------------------------------------------------
__global__ void k_xnorm() {
    const int b = blockIdx.x;
    const int t = threadIdx.x;            // 0..191
    const int w = t >> 5, lane = t & 31;

    float4 acc = make_float4(0.f, 0.f, 0.f, 0.f);
    #pragma unroll
    for (int z = 0; z < NCHUNK; z++) {
        float4 p = reinterpret_cast<const float4*>(g_part)[((size_t)z * BB + b) * D4 + t];
        acc.x += p.x; acc.y += p.y; acc.z += p.z; acc.w += p.w;
    }
    const float inv = 1.0f / (float)NN;
    float4 v = make_float4(acc.x * inv, acc.y * inv, acc.z * inv, acc.w * inv);

    float ss = v.x * v.x + v.y * v.y + v.z * v.z + v.w * v.w;
    ss = warp_sum(ss);
    __shared__ float sm[6];
    __shared__ float s_rinv;
    if (lane == 0) sm[w] = ss;
    __syncthreads();
    if (t == 0) {
        float tot = 0.f;
        #pragma unroll
        for (int i = 0; i < 6; i++) tot += sm[i];
        s_rinv = 1.0f / sqrtf(fmaxf(tot, 1e-12f));
    }
    __syncthreads();
    const float rinv = s_rinv;
    reinterpret_cast<float4*>(g_xnorm + (size_t)b * DIM)[t] =
        make_float4(v.x * rinv, v.y * rinv, v.z * rinv, v.w * rinv);
}

// ---------------------------------------------------------------------------
// K3/K5: tiled sim GEMM with fused key normalization.
// grid (64 pblocks x 2 btiles), 256 threads (8 warps, 2 prompts per warp).
// which=0: q=g_xnorm -> g_sim1 ; which=1: q=g_resq -> g_sim2.
// sim[p*BB + b] = (1/||key_p||) * (key_p . q_b)
// ---------------------------------------------------------------------------
__global__ void k_sim(const float* __restrict__ keys, int which) {
    const int pb = blockIdx.x;            // 16 prompts per block
    const int bt = blockIdx.y;            // 32 queries per tile
    const int t = threadIdx.x;
    const int w = t >> 5, lane = t & 31;

    extern __shared__ float4 sq[];        // [32][QSTR] float4
    const float* qbase = which ? g_resq : g_xnorm;
    float* simout = which ? g_sim2 : g_sim1;

    for (int i = t; i < 32 * D4; i += 256) {
        const int r = i / D4, c = i % D4;
        sq[r * QSTR + c] =
            reinterpret_cast<const float4*>(qbase + (size_t)(bt * 32 + r) * DIM)[c];
    }
    __syncthreads();

    const int p0 = pb * 16 + w * 2;
    const float4* k0 = reinterpret_cast<const float4*>(keys + (size_t)p0 * DIM);
    const float4* k1 = k0 + D4;

    // key norms (coalesced pass + warp reduce)
    float s0 = 0.f, s1 = 0.f;
    #pragma unroll
    for (int jj = 0; jj < 6; jj++) {
        float4 a = k0[lane + 32 * jj];
        s0 += a.x * a.x + a.y * a.y + a.z * a.z + a.w * a.w;
        float4 c = k1[lane + 32 * jj];
        s1 += c.x * c.x + c.y * c.y + c.z * c.z + c.w * c.w;
    }
    s0 = warp_sum(s0); s1 = warp_sum(s1);
    const float r0 = 1.0f / sqrtf(fmaxf(s0, 1e-12f));
    const float r1 = 1.0f / sqrtf(fmaxf(s1, 1e-12f));

    // lane owns query row (bt*32 + lane); keys read via uniform (broadcast) loads
    const float4* q = sq + (size_t)lane * QSTR;
    float a0 = 0.f, a1 = 0.f, b0 = 0.f, b1 = 0.f;
    #pragma unroll 4
    for (int j = 0; j < D4; j++) {
        float4 ka = k0[j];
        float4 kb = k1[j];
        float4 qq = q[j];
        a0 += ka.x * qq.x + ka.y * qq.y;
        a1 += ka.z * qq.z + ka.w * qq.w;
        b0 += kb.x * qq.x + kb.y * qq.y;
        b1 += kb.z * qq.z + kb.w * qq.w;
    }
    const int b = bt * 32 + lane;
    simout[(size_t)p0 * BB + b]       = r0 * (a0 + a1);
    simout[(size_t)(p0 + 1) * BB + b] = r1 * (b0 + b1);
}

// ---------------------------------------------------------------------------
// K4/K6: per-b argmax over sim column (tie -> lowest p), optional resq build.
// grid BB, 256 threads.
// which=0: g_sim1 -> g_idx/g_maxsim + build g_resq = pk[idx]-xnorm
// which=1: g_sim2 -> g_ridx/g_rmax
// ---------------------------------------------------------------------------
__global__ void k_pick(const float* __restrict__ pk, int which) {
    const int b = blockIdx.x;
    const int t = threadIdx.x;            // 0..255
    const float* sim = which ? g_sim2 : g_sim1;

    float best = -3.4e38f; int bi = 0;
    #pragma unroll
    for (int p = t; p < POOL; p += 256) {
        float v = sim[(size_t)p * BB + b];
        if (v > best) { best = v; bi = p; }   // ascending p -> lowest index kept on tie
    }

    __shared__ float sv[256];
    __shared__ int   si[256];
    sv[t] = best; si[t] = bi;
    __syncthreads();
    #pragma unroll
    for (int s = 128; s > 0; s >>= 1) {
        if (t < s) {
            float ov = sv[t + s]; int oi = si[t + s];
            if (ov > sv[t] || (ov == sv[t] && oi < si[t])) { sv[t] = ov; si[t] = oi; }
        }
        __syncthreads();
    }

    __shared__ int s_idx;
    if (t == 0) {
        if (which == 0) { g_idx[b] = si[0]; g_maxsim[b] = sv[0]; }
        else            { g_ridx[b] = si[0]; g_rmax[b] = sv[0]; }
        s_idx = si[0];
    }
    if (which == 0) {
        __syncthreads();
        const int idx = s_idx;
        if (t < D4) {
            float4 a  = reinterpret_cast<const float4*>(pk + (size_t)idx * DIM)[t];
            float4 xn = reinterpret_cast<const float4*>(g_xnorm + (size_t)b * DIM)[t];
            reinterpret_cast<float4*>(g_resq + (size_t)b * DIM)[t] =
                make_float4(a.x - xn.x, a.y - xn.y, a.z - xn.z, a.w - xn.w);
        }
    }
}

// ---------------------------------------------------------------------------
// K7: gather winning prompts + scalar loss. grid BB, 256 threads.
// ---------------------------------------------------------------------------
__global__ void k_gather(const float* __restrict__ prompt,
                         const float* __restrict__ rprompt,
                         float* __restrict__ out,
                         long long out_size) {
    const int b = blockIdx.x;
    const int t = threadIdx.x;            // 256 threads
    const int idx  = g_idx[b];
    const int ridx = g_ridx[b];

    const float4* s1 = reinterpret_cast<const float4*>(rprompt + (size_t)ridx * LEN * DIM);
    const float4* s2 = reinterpret_cast<const float4*>(prompt  + (size_t)idx  * LEN * DIM);
    float4* dst = reinterpret_cast<float4*>(out + (size_t)b * ROW * DIM);

    const int SEG = LEN * DIM / 4;        // 3072
    #pragma unroll 4
    for (int i = t; i < SEG; i += 256) dst[i] = s1[i];
    #pragma unroll 4
    for (int i = t; i < SEG; i += 256) dst[SEG + i] = s2[i];

    if (b == 0 && t == 0) {
        float s = 0.f;
        for (int i = 0; i < BB; i++) s += g_maxsim[i] + g_rmax[i];
        s *= (1.0f / (float)BB);
        const size_t np = (size_t)BB * ROW * DIM;
        if ((size_t)out_size > np) out[(size_t)out_size - 1] = s;
    }
}

// ---------------------------------------------------------------------------
extern "C" void kernel_launch(void* const* d_in, const int* in_sizes, int n_in,
                              void* d_out, int out_size) {
    const float* x       = (const float*)d_in[0];
    const float* prompt  = (const float*)d_in[1];
    const float* pk      = (const float*)d_in[2];
    const float* rprompt = (const float*)d_in[3];
    const float* rpk     = (const float*)d_in[4];
    float* out = (float*)d_out;

    const int SIM_SMEM = 32 * QSTR * 16;  // 98816 bytes
    static int attr_done = 0;
    if (!attr_done) {
        cudaFuncSetAttribute(k_sim, cudaFuncAttributeMaxDynamicSharedMemorySize, SIM_SMEM);
        attr_done = 1;
    }

    k_mean_copy<<<dim3(BB, NCHUNK), D4>>>(x, out);
    k_xnorm<<<BB, D4>>>();
    k_sim<<<dim3(64, 2), 256, SIM_SMEM>>>(pk, 0);
    k_pick<<<BB, 256>>>(pk, 0);
    k_sim<<<dim3(64, 2), 256, SIM_SMEM>>>(rpk, 1);
    k_pick<<<BB, 256>>>(pk, 1);
    k_gather<<<BB, 256>>>(prompt, rprompt, out, (long long)out_size);
}

// round 7
// speedup vs baseline: 1.3308x; 1.0033x over previous
#include <cuda_runtime.h>
#include <math.h>

#define BB    64
#define NN    2048
#define DIM   768
#define POOL  1024
#define LEN   16
#define ROW   2080          // 2*LEN + NN
#define NCHUNK 32
#define CH    64            // NN / NCHUNK
#define D4    192           // DIM / 4
#define QSTR  193           // smem query row stride in float4
#define PBLK  64            // sim prompt-blocks (16 prompts each)

// ---------------- scratch (device globals; only referenced in device code) --
__device__ __align__(16) float g_part[NCHUNK * BB * DIM];
__device__ __align__(16) float g_xnorm[BB * DIM];
__device__ __align__(16) float g_resq[BB * DIM];
__device__ float g_c1v[PBLK * BB];
__device__ int   g_c1i[PBLK * BB];
__device__ float g_c2v[PBLK * BB];
__device__ int   g_c2i[PBLK * BB];
__device__ int   g_idx[BB];
__device__ float g_maxsim[BB];

__device__ __forceinline__ float warp_sum(float v) {
    #pragma unroll
    for (int o = 16; o > 0; o >>= 1) v += __shfl_xor_sync(0xffffffffu, v, o);
    return v;
}

// butterfly argmax (tie -> lowest index); all lanes end with the global best
__device__ __forceinline__ void warp_argmax(float& v, int& i) {
    #pragma unroll
    for (int o = 16; o > 0; o >>= 1) {
        float ov = __shfl_xor_sync(0xffffffffu, v, o);
        int   oi = __shfl_xor_sync(0xffffffffu, i, o);
        if (ov > v || (ov == v && oi < i)) { v = ov; i = oi; }
    }
}

// reduce the 64 per-block candidates for batch b (one warp)
__device__ __forceinline__ void reduce_cand(const float* cv, const int* ci,
                                            int b, int lane, float& v, int& i) {
    float va = cv[lane * BB + b];        int ia = ci[lane * BB + b];
    float vb = cv[(lane + 32) * BB + b]; int ib = ci[(lane + 32) * BB + b];
    if (vb > va || (vb == va && ib < ia)) { va = vb; ia = ib; }
    v = va; i = ia;
    warp_argmax(v, i);
}

// ---------------------------------------------------------------------------
// K1: stream x_embed -> out[:, 32:, :] while accumulating partial sums.
// grid (BB, NCHUNK), 192 threads.
// ---------------------------------------------------------------------------
__global__ void k_mean_copy(const float* __restrict__ x, float* __restrict__ out) {
    const int t = threadIdx.x;            // 0..191
    const int b = blockIdx.x;
    const int z = blockIdx.y;

    const float4* src = reinterpret_cast<const float4*>(
        x + ((size_t)b * NN + (size_t)z * CH) * DIM) + t;
    float4* dst = reinterpret_cast<float4*>(
        out + ((size_t)b * ROW + 2 * LEN + (size_t)z * CH) * DIM) + t;

    float4 s = make_float4(0.f, 0.f, 0.f, 0.f);
    for (int n0 = 0; n0 < CH; n0 += 8) {
        float4 v[8];
        #pragma unroll
        for (int k = 0; k < 8; k++)
            v[k] = __ldcs(src + (size_t)(n0 + k) * D4);
        #pragma unroll
        for (int k = 0; k < 8; k++) {
            s.x += v[k].x; s.y += v[k].y; s.z += v[k].z; s.w += v[k].w;
            __stcs(dst + (size_t)(n0 + k) * D4, v[k]);
        }
    }
    reinterpret_cast<float4*>(g_part)[((size_t)z * BB + b) * D4 + t] = s;
}

// ---------------------------------------------------------------------------
// K2: finalize mean + l2-normalize -> g_xnorm. grid BB, 192 threads.
// ---------------------------------------------------------------------------
__global__ void k_xnorm() {
    const int b = blockIdx.x;
    const int t = threadIdx.x;            // 0..191
    const int w = t >> 5, lane = t & 31;

    float4 acc = make_float4(0.f, 0.f, 0.f, 0.f);
    #pragma unroll
    for (int z = 0; z < NCHUNK; z++) {
        float4 p = reinterpret_cast<const float4*>(g_part)[((size_t)z * BB + b) * D4 + t];
        acc.x += p.x; acc.y += p.y; acc.z += p.z; acc.w += p.w;
    }
    const float inv = 1.0f / (float)NN;
    float4 v = make_float4(acc.x * inv, acc.y * inv, acc.z * inv, acc.w * inv);

    float ss = v.x * v.x + v.y * v.y + v.z * v.z + v.w * v.w;
    ss = warp_sum(ss);
    __shared__ float sm[6];
    __shared__ float s_rinv;
    if (lane == 0) sm[w] = ss;
    __syncthreads();
    if (t == 0) {
        float tot = 0.f;
        #pragma unroll
        for (int i = 0; i < 6; i++) tot += sm[i];
        s_rinv = 1.0f / sqrtf(fmaxf(tot, 1e-12f));
    }
    __syncthreads();
    const float rinv = s_rinv;
    reinterpret_cast<float4*>(g_xnorm + (size_t)b * DIM)[t] =
        make_float4(v.x * rinv, v.y * rinv, v.z * rinv, v.w * rinv);
}

// ---------------------------------------------------------------------------
// K3/K5: tiled sim GEMM, fused key normalization + per-block argmax.
// grid (PBLK, 2), 256 threads (8 warps, 2 prompts per warp, 32 queries/tile).
// Writes per-(pblock,b) best candidate to g_c{1,2}{v,i}.
// ---------------------------------------------------------------------------
__global__ void k_sim(const float* __restrict__ keys, int which) {
    const int pb = blockIdx.x;
    const int bt = blockIdx.y;
    const int t = threadIdx.x;
    const int w = t >> 5, lane = t & 31;

    extern __shared__ float4 sq[];        // [32][QSTR] float4
    const float* qbase = which ? g_resq : g_xnorm;

    for (int i = t; i < 32 * D4; i += 256) {
        const int r = i / D4, c = i % D4;
        sq[r * QSTR + c] =
            reinterpret_cast<const float4*>(qbase + (size_t)(bt * 32 + r) * DIM)[c];
    }
    __syncthreads();

    const int p0 = pb * 16 + w * 2;
    const float4* k0 = reinterpret_cast<const float4*>(keys + (size_t)p0 * DIM);
    const float4* k1 = k0 + D4;

    // key norms (coalesced pass + warp reduce)
    float s0 = 0.f, s1 = 0.f;
    #pragma unroll
    for (int jj = 0; jj < 6; jj++) {
        float4 a = k0[lane + 32 * jj];
        s0 += a.x * a.x + a.y * a.y + a.z * a.z + a.w * a.w;
        float4 c = k1[lane + 32 * jj];
        s1 += c.x * c.x + c.y * c.y + c.z * c.z + c.w * c.w;
    }
    s0 = warp_sum(s0); s1 = warp_sum(s1);
    const float r0 = 1.0f / sqrtf(fmaxf(s0, 1e-12f));
    const float r1 = 1.0f / sqrtf(fmaxf(s1, 1e-12f));

    // lane owns query row (bt*32 + lane); keys via uniform (broadcast) loads
    const float4* q = sq + (size_t)lane * QSTR;
    float a0 = 0.f, a1 = 0.f, b0 = 0.f, b1 = 0.f;
    #pragma unroll 4
    for (int j = 0; j < D4; j++) {
        float4 ka = k0[j];
        float4 kb = k1[j];
        float4 qq = q[j];
        a0 += ka.x * qq.x + ka.y * qq.y;
        a1 += ka.z * qq.z + ka.w * qq.w;
        b0 += kb.x * qq.x + kb.y * qq.y;
        b1 += kb.z * qq.z + kb.w * qq.w;
    }
    const float v0 = r0 * (a0 + a1);
    const float v1 = r1 * (b0 + b1);

    // per-lane best of the warp's 2 prompts (tie -> lower p keeps v0)
    float bv = v0; int bi = p0;
    if (v1 > v0) { bv = v1; bi = p0 + 1; }

    __shared__ float cvs[8][32];
    __shared__ int   cis[8][32];
    cvs[w][lane] = bv; cis[w][lane] = bi;
    __syncthreads();
    if (w == 0) {
        float best = cvs[0][lane]; int besti = cis[0][lane];
        #pragma unroll
        for (int i = 1; i < 8; i++) {
            float ov = cvs[i][lane]; int oi = cis[i][lane];
            if (ov > best || (ov == best && oi < besti)) { best = ov; besti = oi; }
        }
        const int b = bt * 32 + lane;
        if (which) { g_c2v[pb * BB + b] = best; g_c2i[pb * BB + b] = besti; }
        else       { g_c1v[pb * BB + b] = best; g_c1i[pb * BB + b] = besti; }
    }
}

// ---------------------------------------------------------------------------
// K4: reduce level-1 candidates -> idx/maxsim, build residual query.
// grid BB, 192 threads.
// ---------------------------------------------------------------------------
__global__ void k_resq(const float* __restrict__ pk) {
    const int b = blockIdx.x;
    const int t = threadIdx.x;            // 0..191
    __shared__ int s_idx;
    if (t < 32) {
        float v; int i;
        reduce_cand(g_c1v, g_c1i, b, t, v, i);
        if (t == 0) { g_idx[b] = i; g_maxsim[b] = v; s_idx = i; }
    }
    __syncthreads();
    const int idx = s_idx;
    float4 a  = reinterpret_cast<const float4*>(pk + (size_t)idx * DIM)[t];
    float4 xn = reinterpret_cast<const float4*>(g_xnorm + (size_t)b * DIM)[t];
    reinterpret_cast<float4*>(g_resq + (size_t)b * DIM)[t] =
        make_float4(a.x - xn.x, a.y - xn.y, a.z - xn.z, a.w - xn.w);
}

// ---------------------------------------------------------------------------
// K6: reduce level-2 candidates, gather winning prompts, write scalar loss.
// grid BB, 256 threads.
// ---------------------------------------------------------------------------
__global__ void k_gather(const float* __restrict__ prompt,
                         const float* __restrict__ rprompt,
                         float* __restrict__ out,
                         long long out_size) {
    const int b = blockIdx.x;
    const int t = threadIdx.x;            // 256 threads
    __shared__ int s_ridx;
    if (t < 32) {
        float v; int i;
        reduce_cand(g_c2v, g_c2i, b, t, v, i);
        if (t == 0) s_ridx = i;
    }
    __syncthreads();
    const int idx  = g_idx[b];
    const int ridx = s_ridx;

    const float4* s1 = reinterpret_cast<const float4*>(rprompt + (size_t)ridx * LEN * DIM);
    const float4* s2 = reinterpret_cast<const float4*>(prompt  + (size_t)idx  * LEN * DIM);
    float4* dst = reinterpret_cast<float4*>(out + (size_t)b * ROW * DIM);

    const int SEG = LEN * DIM / 4;        // 3072
    #pragma unroll 4
    for (int i = t; i < SEG; i += 256) dst[i] = s1[i];
    #pragma unroll 4
    for (int i = t; i < SEG; i += 256) dst[SEG + i] = s2[i];

    // scalar: block 0, threads 0..63 each reduce batch t's level-2 candidates
    if (b == 0) {
        __shared__ float psum[64];
        if (t < 64) {
            float v = g_c2v[t]; int i = g_c2i[t];
            #pragma unroll 8
            for (int pbk = 1; pbk < PBLK; pbk++) {
                float ov = g_c2v[pbk * BB + t]; int oi = g_c2i[pbk * BB + t];
                if (ov > v || (ov == v && oi < i)) { v = ov; i = oi; }
            }
            psum[t] = g_maxsim[t] + v;
        }
        __syncthreads();
        if (t == 0) {
            float s = 0.f;
            #pragma unroll
            for (int i = 0; i < 64; i++) s += psum[i];
            s *= (1.0f / (float)BB);
            const size_t np = (size_t)BB * ROW * DIM;
            if ((size_t)out_size > np) out[(size_t)out_size - 1] = s;
        }
    }
}

// ---------------------------------------------------------------------------
extern "C" void kernel_launch(void* const* d_in, const int* in_sizes, int n_in,
                              void* d_out, int out_size) {
    const float* x       = (const float*)d_in[0];
    const float* prompt  = (const float*)d_in[1];
    const float* pk      = (const float*)d_in[2];
    const float* rprompt = (const float*)d_in[3];
    const float* rpk     = (const float*)d_in[4];
    float* out = (float*)d_out;

    const int SIM_SMEM = 32 * QSTR * 16;  // 98816 bytes
    static int attr_done = 0;
    if (!attr_done) {
        cudaFuncSetAttribute(k_sim, cudaFuncAttributeMaxDynamicSharedMemorySize, SIM_SMEM);
        attr_done = 1;
    }

    k_mean_copy<<<dim3(BB, NCHUNK), D4>>>(x, out);
    k_xnorm<<<BB, D4>>>();
    k_sim<<<dim3(PBLK, 2), 256, SIM_SMEM>>>(pk, 0);
    k_resq<<<BB, D4>>>(pk);
    k_sim<<<dim3(PBLK, 2), 256, SIM_SMEM>>>(rpk, 1);
    k_gather<<<BB, 256>>>(prompt, rprompt, out, (long long)out_size);
}